// round 7
// baseline (speedup 1.0000x reference)
#include <cuda_runtime.h>
#include <stdint.h>
#include <math.h>

// ---------------------------------------------------------------------------
// DetectionTargetLayer (Mask R-CNN) — exact replication of the JAX reference.
// R7: SINGLE persistent kernel (64 co-resident blocks, software grid barriers)
//     + division-free pos/neg classification. All FP output paths byte-
//     identical to the round-5/6 passing versions.
// ---------------------------------------------------------------------------

#define JAX_PARTITIONABLE 1

#define BB     2
#define NPROP  2000
#define NGT    50
#define TRAIN  200
#define PCAP   66
#define NCAP   134
#define MH     28
#define MW     28
#define IMH    1024
#define IMW    1024
#define SORTN  2048
#define POSK_CAP 128
#define NEGK_CAP 512
#define NEG_THR  0.85f

#define GRID_BLOCKS 64
#define BLOCK_THREADS 256

#define ROIS_OFF 0
#define CLS_OFF  (BB*TRAIN*4)
#define DELT_OFF (CLS_OFF + BB*TRAIN)
#define MASK_OFF (DELT_OFF + BB*TRAIN*4)

#define NEG_RATIO_F ((float)(1.0/0.33))   // np.float32(1.0/ROI_POS_RATIO)
#define STEPC (1023.0f / 27.0f)           // folded constant rn(1023/27)

struct Keys { uint32_t kp0[BB], kp1[BB], kn0[BB], kn1[BB]; };

__host__ __device__ __forceinline__ uint32_t rotl32(uint32_t v, int r) {
    return (v << r) | (v >> (32 - r));
}

__host__ __device__ __forceinline__ void threefry2x32(
    uint32_t k0, uint32_t k1, uint32_t x0, uint32_t x1,
    uint32_t* o0, uint32_t* o1)
{
    uint32_t ks2 = k0 ^ k1 ^ 0x1BD11BDAu;
    x0 += k0; x1 += k1;
#define TF_R(r) { x0 += x1; x1 = rotl32(x1, (r)); x1 ^= x0; }
    TF_R(13) TF_R(15) TF_R(26) TF_R(6)   x0 += k1;  x1 += ks2 + 1u;
    TF_R(17) TF_R(29) TF_R(16) TF_R(24)  x0 += ks2; x1 += k0 + 2u;
    TF_R(13) TF_R(15) TF_R(26) TF_R(6)   x0 += k0;  x1 += k1 + 3u;
    TF_R(17) TF_R(29) TF_R(16) TF_R(24)  x0 += k1;  x1 += ks2 + 4u;
    TF_R(13) TF_R(15) TF_R(26) TF_R(6)   x0 += ks2; x1 += k0 + 5u;
#undef TF_R
    *o0 = x0; *o1 = x1;
}

__device__ __forceinline__ float bits_to_uniform(uint32_t bits) {
    return __uint_as_float((bits >> 9) | 0x3f800000u) - 1.0f;
}

__device__ __forceinline__ float uniform_at(uint32_t k0, uint32_t k1, int i) {
#if JAX_PARTITIONABLE
    uint32_t o0, o1;
    threefry2x32(k0, k1, 0u, (uint32_t)i, &o0, &o1);
    return bits_to_uniform(o0 ^ o1);
#else
    uint32_t o0, o1;
    if (i < NPROP / 2) {
        threefry2x32(k0, k1, (uint32_t)i, (uint32_t)(i + NPROP / 2), &o0, &o1);
        return bits_to_uniform(o0);
    } else {
        threefry2x32(k0, k1, (uint32_t)(i - NPROP / 2), (uint32_t)i, &o0, &o1);
        return bits_to_uniform(o1);
    }
#endif
}

// Exact IoU (used for argmax path — matches reference arithmetic).
__device__ __forceinline__ float iou_f(
    float ay1, float ax1, float ay2, float ax2,
    float by1, float bx1, float by2, float bx2)
{
    float ih = fmaxf(fminf(ay2, by2) - fmaxf(ay1, by1), 0.0f);
    float iw = fmaxf(fminf(ax2, bx2) - fmaxf(ax1, bx1), 0.0f);
    float inter = __fmul_rn(ih, iw);
    float a1 = __fmul_rn(ay2 - ay1, ax2 - ax1);
    float a2 = __fmul_rn(by2 - by1, bx2 - bx1);
    float uni = (a1 + a2) - inter;
    return (uni > 0.0f) ? __fdiv_rn(inter, uni) : 0.0f;
}

// Division-free: inter & union only.
__device__ __forceinline__ void iou_parts(
    float ay1, float ax1, float ay2, float ax2,
    float by1, float bx1, float by2, float bx2,
    float* inter_o, float* uni_o)
{
    float ih = fmaxf(fminf(ay2, by2) - fmaxf(ay1, by1), 0.0f);
    float iw = fmaxf(fminf(ax2, bx2) - fmaxf(ax1, bx1), 0.0f);
    float inter = __fmul_rn(ih, iw);
    float a1 = __fmul_rn(ay2 - ay1, ax2 - ax1);
    float a2 = __fmul_rn(by2 - by1, bx2 - bx1);
    *inter_o = inter;
    *uni_o = (a1 + a2) - inter;
}

// Map float -> uint32 such that ascending uint = DESCENDING float.
__device__ __forceinline__ uint32_t desc_map(float f) {
    uint32_t u = __float_as_uint(f);
    uint32_t m = (u & 0x80000000u) ? ~u : (u | 0x80000000u);
    return ~m;
}
__device__ __forceinline__ unsigned long long mk_key(float f, int idx) {
    return ((unsigned long long)desc_map(f) << 32) | (uint32_t)idx;
}

// staging
__device__ float g_pscore[BB][NPROP];
__device__ float g_nscore[BB][NPROP];
__device__ float g_pos_rois[BB][PCAP][4];
__device__ int   g_assign[BB][PCAP];
__device__ int   g_p[BB];

// grid barrier state (replay-safe: release counter is monotonic)
__device__ int g_bar_cnt = 0;
__device__ int g_bar_rel = 0;

__device__ __forceinline__ void grid_barrier(int target) {
    __syncthreads();
    if (threadIdx.x == 0) {
        __threadfence();
        int t = atomicAdd(&g_bar_cnt, 1);
        if (t == GRID_BLOCKS - 1) {
            atomicExch(&g_bar_cnt, 0);   // all blocks have arrived
            __threadfence();
            atomicAdd(&g_bar_rel, 1);
        }
        while (atomicAdd(&g_bar_rel, 0) < target) { }
        __threadfence();
    }
    __syncthreads();
}

// Ascending bitonic sort of SZ u64 keys in shared (SZ power of 2).
__device__ __forceinline__ void bitonic_sort_u64(unsigned long long* key, int SZ) {
    for (int k = 2; k <= SZ; k <<= 1) {
        for (int j = k >> 1; j > 0; j >>= 1) {
            __syncthreads();
            for (int t = threadIdx.x; t < SZ; t += blockDim.x) {
                int l = t ^ j;
                if (l > t) {
                    unsigned long long a = key[t], bk = key[l];
                    bool up = ((t & k) == 0);
                    if ((a > bk) == up) { key[t] = bk; key[l] = a; }
                }
            }
        }
    }
    __syncthreads();
}

// ---------------------------------------------------------------------------
__global__ __launch_bounds__(BLOCK_THREADS)
void dtl_fused(const float* __restrict__ proposals,
               const int*   __restrict__ gt_class_ids,
               const float* __restrict__ gt_boxes,
               const float* __restrict__ gt_masks,
               float* __restrict__ out,
               Keys keys)
{
    const int tid = threadIdx.x;
    const int bid = blockIdx.x;

    __shared__ float s_gt[BB][NGT][4];
    __shared__ int   s_cls[BB][NGT];
    __shared__ int   s_noncrowd[BB][NGT];
    __shared__ int   s_crowd[BB][NGT];
    __shared__ unsigned long long posk[POSK_CAP];
    __shared__ unsigned long long negk[NEGK_CAP];
    __shared__ unsigned long long bigk[SORTN];
    __shared__ int s_np, s_cneg, s_nthr, s_rel0;

    if (tid == 0) {
        s_rel0 = g_bar_rel;        // stable at kernel entry (replays serialized)
        s_np = 0; s_cneg = 0; s_nthr = 0;
    }

    // -------- load all GT (both images) into shared ----------------------
    for (int t = tid; t < BB * NGT; t += BLOCK_THREADS) {
        int bb = t / NGT, gg = t % NGT;
        float g0 = gt_boxes[((size_t)bb * NGT + gg) * 4 + 0];
        float g1 = gt_boxes[((size_t)bb * NGT + gg) * 4 + 1];
        float g2 = gt_boxes[((size_t)bb * NGT + gg) * 4 + 2];
        float g3 = gt_boxes[((size_t)bb * NGT + gg) * 4 + 3];
        s_gt[bb][gg][0] = g0; s_gt[bb][gg][1] = g1;
        s_gt[bb][gg][2] = g2; s_gt[bb][gg][3] = g3;
        int valid = (fabsf(g0) + fabsf(g1) + fabsf(g2) + fabsf(g3)) > 0.0f;
        int cls = gt_class_ids[(size_t)bb * NGT + gg];
        s_cls[bb][gg] = cls;
        s_noncrowd[bb][gg] = (cls > 0) && valid;
        s_crowd[bb][gg]    = (cls < 0) && valid;
    }
    __syncthreads();
    const int rel0 = s_rel0;

    // ======== PHASE 1: per-proposal classification + scores (all blocks) ==
    {
        int idx = bid * BLOCK_THREADS + tid;
        if (idx < BB * NPROP) {
            int b = idx / NPROP, i = idx % NPROP;
            const float* pr = proposals + ((size_t)b * NPROP + i) * 4;
            float py1 = pr[0], px1 = pr[1], py2 = pr[2], px2 = pr[3];
            bool valid = (fabsf(py1) + fabsf(px1) + fabsf(py2) + fabsf(px2)) > 0.0f;
            bool any_pos = false, any_crowd = false;
            #pragma unroll 5
            for (int g = 0; g < NGT; ++g) {
                float inter, uni;
                iou_parts(py1, px1, py2, px2,
                          s_gt[b][g][0], s_gt[b][g][1], s_gt[b][g][2], s_gt[b][g][3],
                          &inter, &uni);
                bool pos_g = (uni > 0.0f) && (inter >= __fmul_rn(0.5f, uni));
                bool cr_g  = (uni > 0.0f) && (inter >= __fmul_rn(1e-3f, uni));
                if (s_noncrowd[b][g] && pos_g) any_pos = true;
                if (s_crowd[b][g] && cr_g)     any_crowd = true;
            }
            bool pos = valid && any_pos;
            bool neg = valid && !any_pos && !any_crowd;
            g_pscore[b][i] = pos ? uniform_at(keys.kp0[b], keys.kp1[b], i) : -1.0f;
            g_nscore[b][i] = neg ? uniform_at(keys.kn0[b], keys.kn1[b], i) : -1.0f;
        }
    }
    grid_barrier(rel0 + 1);

    // ======== PHASE 2: selection + rois/class/deltas (blocks 0..BB-1) ====
    if (bid < BB) {
        const int b = bid;

        // compaction
        for (int i = tid; i < NPROP; i += BLOCK_THREADS) {
            float ps = g_pscore[b][i];
            if (ps >= 0.0f) {
                int slot = atomicAdd(&s_np, 1);
                if (slot < POSK_CAP) posk[slot] = mk_key(ps, i);
            }
            float ns = g_nscore[b][i];
            if (ns >= 0.0f) {
                atomicAdd(&s_cneg, 1);
                if (ns > NEG_THR) {
                    int slot = atomicAdd(&s_nthr, 1);
                    if (slot < NEGK_CAP) negk[slot] = mk_key(ns, i);
                }
            }
        }
        __syncthreads();

        const int np_total = s_np;
        const int cneg     = s_cneg;
        const int nthr     = s_nthr;
        const int p = min(np_total, PCAP);
        const int needed = (int)(NEG_RATIO_F * (float)p) - p;
        const int n = min(min(cneg, needed), NCAP);

        // positive top-k
        const unsigned long long* psorted;
        if (np_total <= POSK_CAP) {
            for (int t = tid; t < POSK_CAP; t += BLOCK_THREADS)
                if (t >= np_total) posk[t] = 0xFFFFFFFFFFFFFFFFull;
            __syncthreads();
            bitonic_sort_u64(posk, POSK_CAP);
            psorted = posk;
        } else {
            for (int t = tid; t < SORTN; t += BLOCK_THREADS)
                bigk[t] = (t < NPROP) ? mk_key(g_pscore[b][t], t)
                                      : 0xFFFFFFFFFFFFFFFFull;
            __syncthreads();
            bitonic_sort_u64(bigk, SORTN);
            psorted = bigk;
        }

        unsigned long long my_pos_key = (tid < PCAP) ? psorted[tid] : 0;
        __syncthreads();

        // negative top-k
        const unsigned long long* nsorted;
        if (nthr >= n && nthr <= NEGK_CAP) {
            for (int t = tid; t < NEGK_CAP; t += BLOCK_THREADS)
                if (t >= nthr) negk[t] = 0xFFFFFFFFFFFFFFFFull;
            __syncthreads();
            bitonic_sort_u64(negk, NEGK_CAP);
            nsorted = negk;
        } else {
            for (int t = tid; t < SORTN; t += BLOCK_THREADS)
                bigk[t] = (t < NPROP) ? mk_key(g_nscore[b][t], t)
                                      : 0xFFFFFFFFFFFFFFFFull;
            __syncthreads();
            bitonic_sort_u64(bigk, SORTN);
            nsorted = bigk;
        }

        float* rois_o = out + ROIS_OFF + (size_t)b * TRAIN * 4;
        float* cls_o  = out + CLS_OFF  + (size_t)b * TRAIN;
        float* del_o  = out + DELT_OFF + (size_t)b * TRAIN * 4;

        for (int t = tid; t < TRAIN * 4; t += BLOCK_THREADS) { rois_o[t] = 0.0f; del_o[t] = 0.0f; }
        for (int t = tid; t < TRAIN;     t += BLOCK_THREADS) { cls_o[t] = 0.0f; }

        // positives
        if (tid < PCAP && tid < p) {
            const int j = tid;
            int i = (int)(uint32_t)my_pos_key;
            const float* pr = proposals + ((size_t)b * NPROP + i) * 4;
            float ry1 = pr[0], rx1 = pr[1], ry2 = pr[2], rx2 = pr[3];

            int a = 0; float best = -1.0f;
            for (int g = 0; g < NGT; ++g) {
                float ov = s_noncrowd[b][g]
                         ? iou_f(ry1, rx1, ry2, rx2,
                                 s_gt[b][g][0], s_gt[b][g][1], s_gt[b][g][2], s_gt[b][g][3])
                         : -1.0f;
                if (ov > best) { best = ov; a = g; }
            }

            rois_o[j * 4 + 0] = ry1; rois_o[j * 4 + 1] = rx1;
            rois_o[j * 4 + 2] = ry2; rois_o[j * 4 + 3] = rx2;

            float h  = ry2 - ry1,  w  = rx2 - rx1;
            float cy = ry1 + 0.5f * h, cx = rx1 + 0.5f * w;
            float gy1 = s_gt[b][a][0], gx1 = s_gt[b][a][1];
            float gy2 = s_gt[b][a][2], gx2 = s_gt[b][a][3];
            float gh = gy2 - gy1, gw = gx2 - gx1;
            float gcy = gy1 + 0.5f * gh, gcx = gx1 + 0.5f * gw;
            del_o[j * 4 + 0] = __fmul_rn(__fdiv_rn(gcy - cy, h), 10.0f);
            del_o[j * 4 + 1] = __fmul_rn(__fdiv_rn(gcx - cx, w), 10.0f);
            del_o[j * 4 + 2] = __fmul_rn(logf(__fdiv_rn(gh, h)), 5.0f);
            del_o[j * 4 + 3] = __fmul_rn(logf(__fdiv_rn(gw, w)), 5.0f);

            cls_o[j] = (float)s_cls[b][a];

            g_pos_rois[b][j][0] = ry1; g_pos_rois[b][j][1] = rx1;
            g_pos_rois[b][j][2] = ry2; g_pos_rois[b][j][3] = rx2;
            g_assign[b][j] = a;
        }

        // negatives (tid range fits 256 threads: j = tid - 66 not needed;
        // reuse low tids after positives — disjoint output rows)
        if (tid < NCAP && tid < n) {
            const int j = tid;
            int i = (int)(uint32_t)nsorted[j];
            const float* pr = proposals + ((size_t)b * NPROP + i) * 4;
            const int row = p + j;
            rois_o[row * 4 + 0] = pr[0]; rois_o[row * 4 + 1] = pr[1];
            rois_o[row * 4 + 2] = pr[2]; rois_o[row * 4 + 3] = pr[3];
        }

        if (tid == 0) g_p[b] = p;
    }
    grid_barrier(rel0 + 2);

    // ======== PHASE 3: masks (all blocks, striped over pixels) ===========
    const int total_px = BB * TRAIN * MH * MW;
    for (int gidx = bid * BLOCK_THREADS + tid; gidx < total_px;
         gidx += GRID_BLOCKS * BLOCK_THREADS) {
        const int roi = gidx / (MH * MW);
        const int pix = gidx % (MH * MW);
        const int b = roi / TRAIN;
        const int j = roi % TRAIN;
        float* mo = out + MASK_OFF + (size_t)roi * (MH * MW) + pix;

        if (j >= g_p[b]) { *mo = 0.0f; continue; }

        const int r = pix / MW, c = pix % MW;
        const float y1 = g_pos_rois[b][j][0], x1 = g_pos_rois[b][j][1];
        const float y2 = g_pos_rois[b][j][2], x2 = g_pos_rois[b][j][3];
        const int g = g_assign[b][j];

        float ybase = __fmul_rn(y1, 1023.0f);
        float ystep = __fmul_rn(y2 - y1, STEPC);
        float fy    = __fadd_rn(ybase, __fmul_rn((float)r, ystep));
        float yf0 = floorf(fy);
        float wy  = fy - yf0;
        int y0i = (int)fminf(fmaxf(yf0, 0.0f), 1023.0f);
        int y1i = (int)fminf(fmaxf(yf0 + 1.0f, 0.0f), 1023.0f);
        bool vy = (fy >= 0.0f) && (fy <= 1023.0f);

        float xbase = __fmul_rn(x1, 1023.0f);
        float xstep = __fmul_rn(x2 - x1, STEPC);
        float fx    = __fadd_rn(xbase, __fmul_rn((float)c, xstep));
        float xf0 = floorf(fx);
        float wx  = fx - xf0;
        int x0i = (int)fminf(fmaxf(xf0, 0.0f), 1023.0f);
        int x1i = (int)fminf(fmaxf(xf0 + 1.0f, 0.0f), 1023.0f);
        bool vx = (fx >= 0.0f) && (fx <= 1023.0f);

        if (!(vy && vx)) { *mo = 0.0f; continue; }

        size_t rb0 = ((size_t)(b * IMH + y0i)) * IMW;
        size_t rb1 = ((size_t)(b * IMH + y1i)) * IMW;
        float m00 = __ldg(&gt_masks[(rb0 + x0i) * NGT + g]);
        float m01 = __ldg(&gt_masks[(rb0 + x1i) * NGT + g]);
        float m10 = __ldg(&gt_masks[(rb1 + x0i) * NGT + g]);
        float m11 = __ldg(&gt_masks[(rb1 + x1i) * NGT + g]);
        float omwx = 1.0f - wx, omwy = 1.0f - wy;
        float top = __fadd_rn(__fmul_rn(m00, omwx), __fmul_rn(m01, wx));
        float bot = __fadd_rn(__fmul_rn(m10, omwx), __fmul_rn(m11, wx));
        float v   = __fadd_rn(__fmul_rn(top, omwy), __fmul_rn(bot, wy));
        *mo = rintf(v);   // round half to even
    }
}

// ---------------------------------------------------------------------------
static void compute_keys(Keys* K) {
#if JAX_PARTITIONABLE
    for (int b = 0; b < BB; b++) {
        uint32_t kb0, kb1;
        threefry2x32(0u, 42u, 0u, (uint32_t)b, &kb0, &kb1);
        threefry2x32(kb0, kb1, 0u, 0u, &K->kp0[b], &K->kp1[b]);
        threefry2x32(kb0, kb1, 0u, 1u, &K->kn0[b], &K->kn1[b]);
    }
#else
    uint32_t a0, b0, a1, b1;
    threefry2x32(0u, 42u, 0u, 2u, &a0, &b0);
    threefry2x32(0u, 42u, 1u, 3u, &a1, &b1);
    uint32_t kb[BB][2] = { { a0, a1 }, { b0, b1 } };
    for (int b = 0; b < BB; b++) {
        uint32_t c0, d0, c1, d1;
        threefry2x32(kb[b][0], kb[b][1], 0u, 2u, &c0, &d0);
        threefry2x32(kb[b][0], kb[b][1], 1u, 3u, &c1, &d1);
        K->kp0[b] = c0; K->kp1[b] = c1;
        K->kn0[b] = d0; K->kn1[b] = d1;
    }
#endif
}

extern "C" void kernel_launch(void* const* d_in, const int* in_sizes, int n_in,
                              void* d_out, int out_size)
{
    const float* proposals    = (const float*)d_in[0];
    const int*   gt_class_ids = (const int*)d_in[1];
    const float* gt_boxes     = (const float*)d_in[2];
    const float* gt_masks     = (const float*)d_in[3];
    float* out = (float*)d_out;

    Keys keys;
    compute_keys(&keys);

    dtl_fused<<<GRID_BLOCKS, BLOCK_THREADS>>>(proposals, gt_class_ids, gt_boxes,
                                              gt_masks, out, keys);
}

// round 8
// speedup vs baseline: 2.6532x; 2.6532x over previous
#include <cuda_runtime.h>
#include <stdint.h>
#include <math.h>

// ---------------------------------------------------------------------------
// DetectionTargetLayer (Mask R-CNN) — exact replication of the JAX reference.
// R8: two kernels (proven structure). Main kernel uses DIVISION-FREE pos/neg
// classification (validated bit-exact in R7) with scores in shared memory;
// FDIV remains only in the 66-thread argmax/deltas path (reference-exact).
// ---------------------------------------------------------------------------

#define JAX_PARTITIONABLE 1

#define BB     2
#define NPROP  2000
#define NGT    50
#define TRAIN  200
#define PCAP   66
#define NCAP   134
#define MH     28
#define MW     28
#define IMH    1024
#define IMW    1024
#define SORTN  2048
#define POSK_CAP 128
#define NEGK_CAP 512
#define NEG_THR  0.85f

#define ROIS_OFF 0
#define CLS_OFF  (BB*TRAIN*4)
#define DELT_OFF (CLS_OFF + BB*TRAIN)
#define MASK_OFF (DELT_OFF + BB*TRAIN*4)

#define NEG_RATIO_F ((float)(1.0/0.33))   // np.float32(1.0/ROI_POS_RATIO)
#define STEPC (1023.0f / 27.0f)           // folded constant rn(1023/27)

struct Keys { uint32_t kp0[BB], kp1[BB], kn0[BB], kn1[BB]; };

__host__ __device__ __forceinline__ uint32_t rotl32(uint32_t v, int r) {
    return (v << r) | (v >> (32 - r));
}

__host__ __device__ __forceinline__ void threefry2x32(
    uint32_t k0, uint32_t k1, uint32_t x0, uint32_t x1,
    uint32_t* o0, uint32_t* o1)
{
    uint32_t ks2 = k0 ^ k1 ^ 0x1BD11BDAu;
    x0 += k0; x1 += k1;
#define TF_R(r) { x0 += x1; x1 = rotl32(x1, (r)); x1 ^= x0; }
    TF_R(13) TF_R(15) TF_R(26) TF_R(6)   x0 += k1;  x1 += ks2 + 1u;
    TF_R(17) TF_R(29) TF_R(16) TF_R(24)  x0 += ks2; x1 += k0 + 2u;
    TF_R(13) TF_R(15) TF_R(26) TF_R(6)   x0 += k0;  x1 += k1 + 3u;
    TF_R(17) TF_R(29) TF_R(16) TF_R(24)  x0 += k1;  x1 += ks2 + 4u;
    TF_R(13) TF_R(15) TF_R(26) TF_R(6)   x0 += ks2; x1 += k0 + 5u;
#undef TF_R
    *o0 = x0; *o1 = x1;
}

__device__ __forceinline__ float bits_to_uniform(uint32_t bits) {
    return __uint_as_float((bits >> 9) | 0x3f800000u) - 1.0f;
}

__device__ __forceinline__ float uniform_at(uint32_t k0, uint32_t k1, int i) {
#if JAX_PARTITIONABLE
    uint32_t o0, o1;
    threefry2x32(k0, k1, 0u, (uint32_t)i, &o0, &o1);
    return bits_to_uniform(o0 ^ o1);
#else
    uint32_t o0, o1;
    if (i < NPROP / 2) {
        threefry2x32(k0, k1, (uint32_t)i, (uint32_t)(i + NPROP / 2), &o0, &o1);
        return bits_to_uniform(o0);
    } else {
        threefry2x32(k0, k1, (uint32_t)(i - NPROP / 2), (uint32_t)i, &o0, &o1);
        return bits_to_uniform(o1);
    }
#endif
}

// Exact IoU (argmax/deltas path — matches reference arithmetic).
__device__ __forceinline__ float iou_f(
    float ay1, float ax1, float ay2, float ax2,
    float by1, float bx1, float by2, float bx2)
{
    float ih = fmaxf(fminf(ay2, by2) - fmaxf(ay1, by1), 0.0f);
    float iw = fmaxf(fminf(ax2, bx2) - fmaxf(ax1, bx1), 0.0f);
    float inter = __fmul_rn(ih, iw);
    float a1 = __fmul_rn(ay2 - ay1, ax2 - ax1);
    float a2 = __fmul_rn(by2 - by1, bx2 - bx1);
    float uni = (a1 + a2) - inter;
    return (uni > 0.0f) ? __fdiv_rn(inter, uni) : 0.0f;
}

// Division-free: intersection and union only (classification path).
__device__ __forceinline__ void iou_parts(
    float ay1, float ax1, float ay2, float ax2,
    float by1, float bx1, float by2, float bx2,
    float* inter_o, float* uni_o)
{
    float ih = fmaxf(fminf(ay2, by2) - fmaxf(ay1, by1), 0.0f);
    float iw = fmaxf(fminf(ax2, bx2) - fmaxf(ax1, bx1), 0.0f);
    float inter = __fmul_rn(ih, iw);
    float a1 = __fmul_rn(ay2 - ay1, ax2 - ax1);
    float a2 = __fmul_rn(by2 - by1, bx2 - bx1);
    *inter_o = inter;
    *uni_o = (a1 + a2) - inter;
}

// Map float -> uint32 such that ascending uint = DESCENDING float.
__device__ __forceinline__ uint32_t desc_map(float f) {
    uint32_t u = __float_as_uint(f);
    uint32_t m = (u & 0x80000000u) ? ~u : (u | 0x80000000u);
    return ~m;
}
__device__ __forceinline__ unsigned long long mk_key(float f, int idx) {
    return ((unsigned long long)desc_map(f) << 32) | (uint32_t)idx;
}

// staging between kernels
__device__ float g_pos_rois[BB][PCAP][4];
__device__ int   g_assign[BB][PCAP];
__device__ int   g_p[BB];

// Ascending bitonic sort of SZ u64 keys in shared (SZ power of 2).
__device__ __forceinline__ void bitonic_sort_u64(unsigned long long* key, int SZ) {
    for (int k = 2; k <= SZ; k <<= 1) {
        for (int j = k >> 1; j > 0; j >>= 1) {
            __syncthreads();
            for (int t = threadIdx.x; t < SZ; t += blockDim.x) {
                int l = t ^ j;
                if (l > t) {
                    unsigned long long a = key[t], bk = key[l];
                    bool up = ((t & k) == 0);
                    if ((a > bk) == up) { key[t] = bk; key[l] = a; }
                }
            }
        }
    }
    __syncthreads();
}

// ---------------------------------------------------------------------------
// Kernel 1: scoring (division-free) + selection + rois/class/deltas.
// grid BB x 1024. Scores live in shared; no global staging round-trip.
// ---------------------------------------------------------------------------
__global__ __launch_bounds__(1024)
void dtl_main2(const float* __restrict__ proposals,
               const int*   __restrict__ gt_class_ids,
               const float* __restrict__ gt_boxes,
               float* __restrict__ out,
               Keys keys)
{
    const int b   = blockIdx.x;
    const int tid = threadIdx.x;

    __shared__ float s_gt[NGT][4];
    __shared__ int   s_cls[NGT];
    __shared__ int   s_noncrowd[NGT];
    __shared__ int   s_crowd[NGT];
    __shared__ float s_pscore[NPROP];
    __shared__ float s_nscore[NPROP];
    __shared__ unsigned long long posk[POSK_CAP];
    __shared__ unsigned long long negk[NEGK_CAP];
    __shared__ unsigned long long bigk[SORTN];   // fallback only
    __shared__ int s_np, s_cneg, s_nthr;

    if (tid == 0) { s_np = 0; s_cneg = 0; s_nthr = 0; }
    if (tid < NGT) {
        float g0 = gt_boxes[((size_t)b * NGT + tid) * 4 + 0];
        float g1 = gt_boxes[((size_t)b * NGT + tid) * 4 + 1];
        float g2 = gt_boxes[((size_t)b * NGT + tid) * 4 + 2];
        float g3 = gt_boxes[((size_t)b * NGT + tid) * 4 + 3];
        s_gt[tid][0] = g0; s_gt[tid][1] = g1; s_gt[tid][2] = g2; s_gt[tid][3] = g3;
        int valid = (fabsf(g0) + fabsf(g1) + fabsf(g2) + fabsf(g3)) > 0.0f;
        int cls = gt_class_ids[(size_t)b * NGT + tid];
        s_cls[tid] = cls;
        s_noncrowd[tid] = (cls > 0) && valid;
        s_crowd[tid]    = (cls < 0) && valid;
    }
    __syncthreads();

    // -------- phase A: division-free classification + scores -------------
    for (int i = tid; i < NPROP; i += blockDim.x) {
        const float* pr = proposals + ((size_t)b * NPROP + i) * 4;
        float py1 = pr[0], px1 = pr[1], py2 = pr[2], px2 = pr[3];
        bool valid = (fabsf(py1) + fabsf(px1) + fabsf(py2) + fabsf(px2)) > 0.0f;
        bool any_pos = false, any_crowd = false;
        #pragma unroll 5
        for (int g = 0; g < NGT; ++g) {
            float inter, uni;
            iou_parts(py1, px1, py2, px2,
                      s_gt[g][0], s_gt[g][1], s_gt[g][2], s_gt[g][3],
                      &inter, &uni);
            bool pos_g = (uni > 0.0f) && (inter >= __fmul_rn(0.5f, uni));
            bool cr_g  = (uni > 0.0f) && (inter >= __fmul_rn(1e-3f, uni));
            if (s_noncrowd[g] && pos_g) any_pos = true;
            if (s_crowd[g] && cr_g)     any_crowd = true;
        }
        bool pos = valid && any_pos;
        bool neg = valid && !any_pos && !any_crowd;
        s_pscore[i] = pos ? uniform_at(keys.kp0[b], keys.kp1[b], i) : -1.0f;
        s_nscore[i] = neg ? uniform_at(keys.kn0[b], keys.kn1[b], i) : -1.0f;
    }
    __syncthreads();

    // -------- compaction --------------------------------------------------
    for (int i = tid; i < NPROP; i += blockDim.x) {
        float ps = s_pscore[i];
        if (ps >= 0.0f) {
            int slot = atomicAdd(&s_np, 1);
            if (slot < POSK_CAP) posk[slot] = mk_key(ps, i);
        }
        float ns = s_nscore[i];
        if (ns >= 0.0f) {
            atomicAdd(&s_cneg, 1);
            if (ns > NEG_THR) {
                int slot = atomicAdd(&s_nthr, 1);
                if (slot < NEGK_CAP) negk[slot] = mk_key(ns, i);
            }
        }
    }
    __syncthreads();

    const int np_total = s_np;
    const int cneg     = s_cneg;
    const int nthr     = s_nthr;
    const int p = min(np_total, PCAP);
    const int needed = (int)(NEG_RATIO_F * (float)p) - p;
    const int n = min(min(cneg, needed), NCAP);

    // -------- positive top-k ----------------------------------------------
    const unsigned long long* psorted;
    if (np_total <= POSK_CAP) {
        for (int t = tid; t < POSK_CAP; t += blockDim.x)
            if (t >= np_total) posk[t] = 0xFFFFFFFFFFFFFFFFull;
        __syncthreads();
        bitonic_sort_u64(posk, POSK_CAP);
        psorted = posk;
    } else {
        for (int t = tid; t < SORTN; t += blockDim.x)
            bigk[t] = (t < NPROP) ? mk_key(s_pscore[t], t)
                                  : 0xFFFFFFFFFFFFFFFFull;
        __syncthreads();
        bitonic_sort_u64(bigk, SORTN);
        psorted = bigk;
    }

    unsigned long long my_pos_key = (tid < PCAP) ? psorted[tid] : 0;
    __syncthreads();

    // -------- negative top-k ----------------------------------------------
    const unsigned long long* nsorted;
    if (nthr >= n && nthr <= NEGK_CAP) {
        for (int t = tid; t < NEGK_CAP; t += blockDim.x)
            if (t >= nthr) negk[t] = 0xFFFFFFFFFFFFFFFFull;
        __syncthreads();
        bitonic_sort_u64(negk, NEGK_CAP);
        nsorted = negk;
    } else {
        for (int t = tid; t < SORTN; t += blockDim.x)
            bigk[t] = (t < NPROP) ? mk_key(s_nscore[t], t)
                                  : 0xFFFFFFFFFFFFFFFFull;
        __syncthreads();
        bitonic_sort_u64(bigk, SORTN);
        nsorted = bigk;
    }

    float* rois_o = out + ROIS_OFF + (size_t)b * TRAIN * 4;
    float* cls_o  = out + CLS_OFF  + (size_t)b * TRAIN;
    float* del_o  = out + DELT_OFF + (size_t)b * TRAIN * 4;

    for (int t = tid; t < TRAIN * 4; t += blockDim.x) { rois_o[t] = 0.0f; del_o[t] = 0.0f; }
    for (int t = tid; t < TRAIN;     t += blockDim.x) { cls_o[t] = 0.0f; }

    // -------- positives ---------------------------------------------------
    if (tid < PCAP && tid < p) {
        const int j = tid;
        int i = (int)(uint32_t)my_pos_key;
        const float* pr = proposals + ((size_t)b * NPROP + i) * 4;
        float ry1 = pr[0], rx1 = pr[1], ry2 = pr[2], rx2 = pr[3];

        int a = 0; float best = -1.0f;
        for (int g = 0; g < NGT; ++g) {
            float ov = s_noncrowd[g]
                     ? iou_f(ry1, rx1, ry2, rx2,
                             s_gt[g][0], s_gt[g][1], s_gt[g][2], s_gt[g][3])
                     : -1.0f;
            if (ov > best) { best = ov; a = g; }
        }

        rois_o[j * 4 + 0] = ry1; rois_o[j * 4 + 1] = rx1;
        rois_o[j * 4 + 2] = ry2; rois_o[j * 4 + 3] = rx2;

        float h  = ry2 - ry1,  w  = rx2 - rx1;
        float cy = ry1 + 0.5f * h, cx = rx1 + 0.5f * w;
        float gy1 = s_gt[a][0], gx1 = s_gt[a][1], gy2 = s_gt[a][2], gx2 = s_gt[a][3];
        float gh = gy2 - gy1, gw = gx2 - gx1;
        float gcy = gy1 + 0.5f * gh, gcx = gx1 + 0.5f * gw;
        del_o[j * 4 + 0] = __fmul_rn(__fdiv_rn(gcy - cy, h), 10.0f);
        del_o[j * 4 + 1] = __fmul_rn(__fdiv_rn(gcx - cx, w), 10.0f);
        del_o[j * 4 + 2] = __fmul_rn(logf(__fdiv_rn(gh, h)), 5.0f);
        del_o[j * 4 + 3] = __fmul_rn(logf(__fdiv_rn(gw, w)), 5.0f);

        cls_o[j] = (float)s_cls[a];

        g_pos_rois[b][j][0] = ry1; g_pos_rois[b][j][1] = rx1;
        g_pos_rois[b][j][2] = ry2; g_pos_rois[b][j][3] = rx2;
        g_assign[b][j] = a;
    }

    // -------- negatives: rois rows [p, p+n) -------------------------------
    if (tid >= 128 && tid < 128 + NCAP) {
        const int j = tid - 128;
        if (j < n) {
            int i = (int)(uint32_t)nsorted[j];
            const float* pr = proposals + ((size_t)b * NPROP + i) * 4;
            const int row = p + j;
            rois_o[row * 4 + 0] = pr[0]; rois_o[row * 4 + 1] = pr[1];
            rois_o[row * 4 + 2] = pr[2]; rois_o[row * 4 + 3] = pr[3];
        }
    }

    if (tid == 0) g_p[b] = p;
}

// ---------------------------------------------------------------------------
// Kernel 2: masks — one thread per output pixel (validated in R6/R7).
// ---------------------------------------------------------------------------
__global__ __launch_bounds__(256)
void dtl_masks(const float* __restrict__ gt_masks, float* __restrict__ out)
{
    const int gidx = blockIdx.x * 256 + threadIdx.x;   // < BB*TRAIN*784
    const int roi = gidx / (MH * MW);
    const int pix = gidx % (MH * MW);
    const int b = roi / TRAIN;
    const int j = roi % TRAIN;
    float* mo = out + MASK_OFF + (size_t)roi * (MH * MW) + pix;

    if (j >= g_p[b]) { *mo = 0.0f; return; }

    const int r = pix / MW, c = pix % MW;
    const float y1 = g_pos_rois[b][j][0], x1 = g_pos_rois[b][j][1];
    const float y2 = g_pos_rois[b][j][2], x2 = g_pos_rois[b][j][3];
    const int g = g_assign[b][j];

    float ybase = __fmul_rn(y1, 1023.0f);
    float ystep = __fmul_rn(y2 - y1, STEPC);
    float fy    = __fadd_rn(ybase, __fmul_rn((float)r, ystep));
    float yf0 = floorf(fy);
    float wy  = fy - yf0;
    int y0i = (int)fminf(fmaxf(yf0, 0.0f), 1023.0f);
    int y1i = (int)fminf(fmaxf(yf0 + 1.0f, 0.0f), 1023.0f);
    bool vy = (fy >= 0.0f) && (fy <= 1023.0f);

    float xbase = __fmul_rn(x1, 1023.0f);
    float xstep = __fmul_rn(x2 - x1, STEPC);
    float fx    = __fadd_rn(xbase, __fmul_rn((float)c, xstep));
    float xf0 = floorf(fx);
    float wx  = fx - xf0;
    int x0i = (int)fminf(fmaxf(xf0, 0.0f), 1023.0f);
    int x1i = (int)fminf(fmaxf(xf0 + 1.0f, 0.0f), 1023.0f);
    bool vx = (fx >= 0.0f) && (fx <= 1023.0f);

    if (!(vy && vx)) { *mo = 0.0f; return; }

    size_t rb0 = ((size_t)(b * IMH + y0i)) * IMW;
    size_t rb1 = ((size_t)(b * IMH + y1i)) * IMW;
    float m00 = __ldg(&gt_masks[(rb0 + x0i) * NGT + g]);
    float m01 = __ldg(&gt_masks[(rb0 + x1i) * NGT + g]);
    float m10 = __ldg(&gt_masks[(rb1 + x0i) * NGT + g]);
    float m11 = __ldg(&gt_masks[(rb1 + x1i) * NGT + g]);
    float omwx = 1.0f - wx, omwy = 1.0f - wy;
    float top = __fadd_rn(__fmul_rn(m00, omwx), __fmul_rn(m01, wx));
    float bot = __fadd_rn(__fmul_rn(m10, omwx), __fmul_rn(m11, wx));
    float v   = __fadd_rn(__fmul_rn(top, omwy), __fmul_rn(bot, wy));
    *mo = rintf(v);   // round half to even
}

// ---------------------------------------------------------------------------
static void compute_keys(Keys* K) {
#if JAX_PARTITIONABLE
    for (int b = 0; b < BB; b++) {
        uint32_t kb0, kb1;
        threefry2x32(0u, 42u, 0u, (uint32_t)b, &kb0, &kb1);
        threefry2x32(kb0, kb1, 0u, 0u, &K->kp0[b], &K->kp1[b]);
        threefry2x32(kb0, kb1, 0u, 1u, &K->kn0[b], &K->kn1[b]);
    }
#else
    uint32_t a0, b0, a1, b1;
    threefry2x32(0u, 42u, 0u, 2u, &a0, &b0);
    threefry2x32(0u, 42u, 1u, 3u, &a1, &b1);
    uint32_t kb[BB][2] = { { a0, a1 }, { b0, b1 } };
    for (int b = 0; b < BB; b++) {
        uint32_t c0, d0, c1, d1;
        threefry2x32(kb[b][0], kb[b][1], 0u, 2u, &c0, &d0);
        threefry2x32(kb[b][0], kb[b][1], 1u, 3u, &c1, &d1);
        K->kp0[b] = c0; K->kp1[b] = c1;
        K->kn0[b] = d0; K->kn1[b] = d1;
    }
#endif
}

extern "C" void kernel_launch(void* const* d_in, const int* in_sizes, int n_in,
                              void* d_out, int out_size)
{
    const float* proposals    = (const float*)d_in[0];
    const int*   gt_class_ids = (const int*)d_in[1];
    const float* gt_boxes     = (const float*)d_in[2];
    const float* gt_masks     = (const float*)d_in[3];
    float* out = (float*)d_out;

    Keys keys;
    compute_keys(&keys);

    dtl_main2<<<BB, 1024>>>(proposals, gt_class_ids, gt_boxes, out, keys);
    dtl_masks<<<(BB * TRAIN * MH * MW) / 256, 256>>>(gt_masks, out);
}